// round 13
// baseline (speedup 1.0000x reference)
#include <cuda_runtime.h>

#define NMAX    160000
#define KCOUT   32
#define KCIN    32
#define KTAPS   27
#define WELEMS  (KTAPS * KCIN * KCOUT)   // 27648
#define CBLOCKS 1184                     // 148 SMs x 8 blocks; 4 warps/block -> 4736 warps (1 wave)
#define NWARPS  (CBLOCKS * 4)

// ---- device scratch (no allocations allowed) ----
__device__ float g_conv[(size_t)NMAX * KCOUT];   // pre-BN conv output
__device__ float g_wt[WELEMS];                   // transposed weights [k][c/4][d][c%4]
__device__ float g_psum[CBLOCKS * KCOUT];        // per-block channel sums
__device__ float g_psq [CBLOCKS * KCOUT];        // per-block channel sum-of-squares
__device__ float g_scale[KCOUT];                 // rstd * gamma
__device__ float g_shift[KCOUT];                 // beta - mean * scale

// ---------------------------------------------------------------------------
// K0: transpose weight [k][c][d] -> [k][c>>2][d][c&3] so that lane d can load
//     a float4 covering 4 consecutive c for its output channel (coalesced).
// ---------------------------------------------------------------------------
__global__ void transpose_w_kernel(const float* __restrict__ w) {
    int i = blockIdx.x * blockDim.x + threadIdx.x;
    if (i < WELEMS) {
        int d = i & 31;
        int c = (i >> 5) & 31;
        int k = i >> 10;
        g_wt[k * 1024 + (c >> 2) * 128 + d * 4 + (c & 3)] = w[i];
    }
}

// ---------------------------------------------------------------------------
// K1: sparse conv, occupancy-first version.
//     - center tap (k=13) == row itself (submanifold identity): dense stream
//     - center weights in SMEM (4KB), NOT registers
//     - no software pipeline; 32 warps/SM hide the gather latency
//     - 4 independent accumulators break the FFMA RAW chain
//     - bias omitted (cancels exactly in training-mode BN)
// ---------------------------------------------------------------------------
__global__ __launch_bounds__(128, 8) void conv_kernel(
    const float* __restrict__ feat,   // [N,32]
    const int*   __restrict__ nbr,    // [N,27]
    int n)
{
    __shared__ float4 s_wc[256];      // W[13] as [c/4][d] float4 (c%4 inner) = 4KB
    __shared__ float  s_red[2][4][32];

    const int tid  = threadIdx.x;
    const int lane = tid & 31;
    const int wloc = tid >> 5;
    const int warp = blockIdx.x * 4 + wloc;

    // cooperative load of center-tap weights into SMEM (2 float4 per thread)
    {
        const float4* wsrc = (const float4*)(g_wt + 13 * 1024);
        s_wc[tid]       = __ldg(wsrc + tid);
        s_wc[tid + 128] = __ldg(wsrc + tid + 128);
    }
    __syncthreads();

    const unsigned EXTRA_MASK = ((1u << KTAPS) - 1u) & ~(1u << 13);

    const int per = (n + NWARPS - 1) / NWARPS;   // 34
    const int r0  = warp * per;
    const int r1  = (r0 + per < n) ? (r0 + per) : n;

    float bsum = 0.f, bsq = 0.f;

    for (int row = r0; row < r1; ++row) {
        // issue all 8 feature loads + idx load up front (max MLP)
        const float4* fp = (const float4*)(feat + (long)row * 32);
        float4 f[8];
        #pragma unroll
        for (int t = 0; t < 8; ++t) f[t] = __ldg(fp + t);
        int idx = (lane < KTAPS) ? __ldg(nbr + (long)row * KTAPS + lane) : -1;

        // center tap: SMEM weights, 4 independent accumulator chains
        float a0 = 0.f, a1 = 0.f, a2 = 0.f, a3 = 0.f;
        #pragma unroll
        for (int c4 = 0; c4 < 8; c4 += 4) {
            float4 w0 = s_wc[(c4 + 0) * 32 + lane];
            float4 w1 = s_wc[(c4 + 1) * 32 + lane];
            float4 w2 = s_wc[(c4 + 2) * 32 + lane];
            float4 w3 = s_wc[(c4 + 3) * 32 + lane];
            a0 += f[c4+0].x*w0.x + f[c4+0].y*w0.y + f[c4+0].z*w0.z + f[c4+0].w*w0.w;
            a1 += f[c4+1].x*w1.x + f[c4+1].y*w1.y + f[c4+1].z*w1.z + f[c4+1].w*w1.w;
            a2 += f[c4+2].x*w2.x + f[c4+2].y*w2.y + f[c4+2].z*w2.z + f[c4+2].w*w2.w;
            a3 += f[c4+3].x*w3.x + f[c4+3].y*w3.y + f[c4+3].z*w3.z + f[c4+3].w*w3.w;
        }
        float acc = (a0 + a1) + (a2 + a3);

        // rare extra taps (~0.49/row): loaded weights (L1/L2-resident)
        unsigned m = __ballot_sync(0xffffffffu, idx >= 0) & EXTRA_MASK;
        while (m) {
            int k = __ffs(m) - 1;
            m &= (m - 1);
            int j = __shfl_sync(0xffffffffu, idx, k);

            const float4* fp2 = (const float4*)(feat + (long)j * 32);
            const float4* wp  = (const float4*)(g_wt + k * 1024) + lane;

            float e0 = 0.f, e1 = 0.f;
            #pragma unroll
            for (int h = 0; h < 4; ++h) {
                float4 fa = __ldg(fp2 + 2*h);
                float4 fb = __ldg(fp2 + 2*h + 1);
                float4 wa = __ldg(wp + (2*h) * 32);
                float4 wb = __ldg(wp + (2*h + 1) * 32);
                e0 += fa.x*wa.x + fa.y*wa.y + fa.z*wa.z + fa.w*wa.w;
                e1 += fb.x*wb.x + fb.y*wb.y + fb.z*wb.z + fb.w*wb.w;
            }
            acc += e0 + e1;
        }

        g_conv[(long)row * KCOUT + lane] = acc;
        bsum += acc;
        bsq  += acc * acc;
    }

    // block-level deterministic reduction of BN partials
    s_red[0][wloc][lane] = bsum;
    s_red[1][wloc][lane] = bsq;
    __syncthreads();
    if (tid < 32) {
        float s = 0.f, q = 0.f;
        #pragma unroll
        for (int i = 0; i < 4; ++i) { s += s_red[0][i][tid]; q += s_red[1][i][tid]; }
        g_psum[blockIdx.x * 32 + tid] = s;
        g_psq [blockIdx.x * 32 + tid] = q;
    }
}

// ---------------------------------------------------------------------------
// K2: reduce block partials -> mean/var -> fused scale/shift. Single block.
// ---------------------------------------------------------------------------
__global__ void stats_kernel(const float* __restrict__ gamma,
                             const float* __restrict__ beta,
                             int n)
{
    __shared__ float ss[32][32];
    __shared__ float sq[32][32];
    const int ch = threadIdx.x & 31;
    const int sl = threadIdx.x >> 5;   // 1024 threads -> 32 slices

    float s = 0.f, q = 0.f;
    for (int i = sl; i < CBLOCKS; i += 32) {
        s += g_psum[i * 32 + ch];
        q += g_psq [i * 32 + ch];
    }
    ss[sl][ch] = s;
    sq[sl][ch] = q;
    __syncthreads();

    if (threadIdx.x < 32) {
        float S = 0.f, Q = 0.f;
        #pragma unroll
        for (int i = 0; i < 32; ++i) { S += ss[i][threadIdx.x]; Q += sq[i][threadIdx.x]; }
        float inv_n = 1.f / (float)n;
        float mean  = S * inv_n;
        float var   = Q * inv_n - mean * mean;
        float rstd  = rsqrtf(var + 1e-5f);
        float sc    = rstd * __ldg(gamma + threadIdx.x);
        g_scale[threadIdx.x] = sc;
        g_shift[threadIdx.x] = __ldg(beta + threadIdx.x) - mean * sc;
    }
}

// ---------------------------------------------------------------------------
// K3: elementwise BN-apply + LeakyReLU, float4 vectorized.
// ---------------------------------------------------------------------------
__global__ __launch_bounds__(256) void finalize_kernel(float* __restrict__ out, int n4) {
    int i = blockIdx.x * blockDim.x + threadIdx.x;
    if (i >= n4) return;
    float4 v = ((const float4*)g_conv)[i];
    int cb = (i & 7) * 4;                       // channel base within row
    float4 sc = *(const float4*)(g_scale + cb);
    float4 sh = *(const float4*)(g_shift + cb);
    float4 o;
    o.x = v.x * sc.x + sh.x;
    o.y = v.y * sc.y + sh.y;
    o.z = v.z * sc.z + sh.z;
    o.w = v.w * sc.w + sh.w;
    o.x = (o.x >= 0.f) ? o.x : 0.01f * o.x;
    o.y = (o.y >= 0.f) ? o.y : 0.01f * o.y;
    o.z = (o.z >= 0.f) ? o.z : 0.01f * o.z;
    o.w = (o.w >= 0.f) ? o.w : 0.01f * o.w;
    ((float4*)out)[i] = o;
}

// ---------------------------------------------------------------------------
// kernel_launch — inputs per metadata order:
//   0: features [N,32] f32   1: neighbor_idx [N,27] i32   2: weight [27,32,32] f32
//   3: bias [32] f32 (unused: cancels in training-mode BN)
//   4: gamma [32] f32        5: beta [32] f32
// output: [N,32] f32
// ---------------------------------------------------------------------------
extern "C" void kernel_launch(void* const* d_in, const int* in_sizes, int n_in,
                              void* d_out, int out_size)
{
    const float* feat  = (const float*)d_in[0];
    const int*   nbr   = (const int*)  d_in[1];
    const float* w     = (const float*)d_in[2];
    const float* gamma = (const float*)d_in[4];
    const float* beta  = (const float*)d_in[5];
    float* out = (float*)d_out;

    int n = in_sizes[0] / KCIN;     // number of active voxels
    if (n > NMAX) n = NMAX;

    transpose_w_kernel<<<(WELEMS + 255) / 256, 256>>>(w);
    conv_kernel<<<CBLOCKS, 128>>>(feat, nbr, n);
    stats_kernel<<<1, 1024>>>(gamma, beta, n);
    int n4 = n * (KCOUT / 4);
    finalize_kernel<<<(n4 + 255) / 256, 256>>>(out, n4);
}

// round 14
// speedup vs baseline: 1.0069x; 1.0069x over previous
#include <cuda_runtime.h>

#define NMAX    160000
#define KCOUT   32
#define KCIN    32
#define KTAPS   27
#define WELEMS  (KTAPS * KCIN * KCOUT)   // 27648
#define CBLOCKS 1184                     // 148 SMs x 8 blocks; 4 warps/block -> 4736 warps (1 wave)
#define NWARPS  (CBLOCKS * 4)

// ---- device scratch (no allocations allowed) ----
__device__ float g_conv[(size_t)NMAX * KCOUT];   // pre-BN conv output
__device__ float g_wt[WELEMS];                   // transposed weights [k][c/4][d][c%4]
__device__ float g_psum[CBLOCKS * KCOUT];        // per-block channel sums
__device__ float g_psq [CBLOCKS * KCOUT];        // per-block channel sum-of-squares
__device__ float g_scale[KCOUT];                 // rstd * gamma
__device__ float g_shift[KCOUT];                 // beta - mean * scale

// ---------------------------------------------------------------------------
// K0: transpose weight [k][c][d] -> [k][c>>2][d][c&3] so that lane d can load
//     a float4 covering 4 consecutive c for its output channel (coalesced).
// ---------------------------------------------------------------------------
__global__ void transpose_w_kernel(const float* __restrict__ w) {
    int i = blockIdx.x * blockDim.x + threadIdx.x;
    if (i < WELEMS) {
        int d = i & 31;
        int c = (i >> 5) & 31;
        int k = i >> 10;
        g_wt[k * 1024 + (c >> 2) * 128 + d * 4 + (c & 3)] = w[i];
    }
}

// ---------------------------------------------------------------------------
// K1: sparse conv, occupancy-first version.
//     - center tap (k=13) == row itself (submanifold identity): dense stream
//     - center weights in SMEM (4KB), NOT registers
//     - no software pipeline; 32 warps/SM hide the gather latency
//     - 4 independent accumulators break the FFMA RAW chain
//     - bias omitted (cancels exactly in training-mode BN)
// ---------------------------------------------------------------------------
__global__ __launch_bounds__(128, 8) void conv_kernel(
    const float* __restrict__ feat,   // [N,32]
    const int*   __restrict__ nbr,    // [N,27]
    int n)
{
    __shared__ float4 s_wc[256];      // W[13] as [c/4][d] float4 (c%4 inner) = 4KB
    __shared__ float  s_red[2][4][32];

    const int tid  = threadIdx.x;
    const int lane = tid & 31;
    const int wloc = tid >> 5;
    const int warp = blockIdx.x * 4 + wloc;

    // cooperative load of center-tap weights into SMEM (2 float4 per thread)
    {
        const float4* wsrc = (const float4*)(g_wt + 13 * 1024);
        s_wc[tid]       = __ldg(wsrc + tid);
        s_wc[tid + 128] = __ldg(wsrc + tid + 128);
    }
    __syncthreads();

    const unsigned EXTRA_MASK = ((1u << KTAPS) - 1u) & ~(1u << 13);

    const int per = (n + NWARPS - 1) / NWARPS;   // 34
    const int r0  = warp * per;
    const int r1  = (r0 + per < n) ? (r0 + per) : n;

    float bsum = 0.f, bsq = 0.f;

    for (int row = r0; row < r1; ++row) {
        // issue all 8 feature loads + idx load up front (max MLP)
        const float4* fp = (const float4*)(feat + (long)row * 32);
        float4 f[8];
        #pragma unroll
        for (int t = 0; t < 8; ++t) f[t] = __ldg(fp + t);
        int idx = (lane < KTAPS) ? __ldg(nbr + (long)row * KTAPS + lane) : -1;

        // center tap: SMEM weights, 4 independent accumulator chains
        float a0 = 0.f, a1 = 0.f, a2 = 0.f, a3 = 0.f;
        #pragma unroll
        for (int c4 = 0; c4 < 8; c4 += 4) {
            float4 w0 = s_wc[(c4 + 0) * 32 + lane];
            float4 w1 = s_wc[(c4 + 1) * 32 + lane];
            float4 w2 = s_wc[(c4 + 2) * 32 + lane];
            float4 w3 = s_wc[(c4 + 3) * 32 + lane];
            a0 += f[c4+0].x*w0.x + f[c4+0].y*w0.y + f[c4+0].z*w0.z + f[c4+0].w*w0.w;
            a1 += f[c4+1].x*w1.x + f[c4+1].y*w1.y + f[c4+1].z*w1.z + f[c4+1].w*w1.w;
            a2 += f[c4+2].x*w2.x + f[c4+2].y*w2.y + f[c4+2].z*w2.z + f[c4+2].w*w2.w;
            a3 += f[c4+3].x*w3.x + f[c4+3].y*w3.y + f[c4+3].z*w3.z + f[c4+3].w*w3.w;
        }
        float acc = (a0 + a1) + (a2 + a3);

        // rare extra taps (~0.49/row): loaded weights (L1/L2-resident)
        unsigned m = __ballot_sync(0xffffffffu, idx >= 0) & EXTRA_MASK;
        while (m) {
            int k = __ffs(m) - 1;
            m &= (m - 1);
            int j = __shfl_sync(0xffffffffu, idx, k);

            const float4* fp2 = (const float4*)(feat + (long)j * 32);
            const float4* wp  = (const float4*)(g_wt + k * 1024) + lane;

            float e0 = 0.f, e1 = 0.f;
            #pragma unroll
            for (int h = 0; h < 4; ++h) {
                float4 fa = __ldg(fp2 + 2*h);
                float4 fb = __ldg(fp2 + 2*h + 1);
                float4 wa = __ldg(wp + (2*h) * 32);
                float4 wb = __ldg(wp + (2*h + 1) * 32);
                e0 += fa.x*wa.x + fa.y*wa.y + fa.z*wa.z + fa.w*wa.w;
                e1 += fb.x*wb.x + fb.y*wb.y + fb.z*wb.z + fb.w*wb.w;
            }
            acc += e0 + e1;
        }

        g_conv[(long)row * KCOUT + lane] = acc;
        bsum += acc;
        bsq  += acc * acc;
    }

    // block-level deterministic reduction of BN partials
    s_red[0][wloc][lane] = bsum;
    s_red[1][wloc][lane] = bsq;
    __syncthreads();
    if (tid < 32) {
        float s = 0.f, q = 0.f;
        #pragma unroll
        for (int i = 0; i < 4; ++i) { s += s_red[0][i][tid]; q += s_red[1][i][tid]; }
        g_psum[blockIdx.x * 32 + tid] = s;
        g_psq [blockIdx.x * 32 + tid] = q;
    }
}

// ---------------------------------------------------------------------------
// K2: reduce block partials -> mean/var -> fused scale/shift. Single block.
// ---------------------------------------------------------------------------
__global__ void stats_kernel(const float* __restrict__ gamma,
                             const float* __restrict__ beta,
                             int n)
{
    __shared__ float ss[32][32];
    __shared__ float sq[32][32];
    const int ch = threadIdx.x & 31;
    const int sl = threadIdx.x >> 5;   // 1024 threads -> 32 slices

    float s = 0.f, q = 0.f;
    for (int i = sl; i < CBLOCKS; i += 32) {
        s += g_psum[i * 32 + ch];
        q += g_psq [i * 32 + ch];
    }
    ss[sl][ch] = s;
    sq[sl][ch] = q;
    __syncthreads();

    if (threadIdx.x < 32) {
        float S = 0.f, Q = 0.f;
        #pragma unroll
        for (int i = 0; i < 32; ++i) { S += ss[i][threadIdx.x]; Q += sq[i][threadIdx.x]; }
        float inv_n = 1.f / (float)n;
        float mean  = S * inv_n;
        float var   = Q * inv_n - mean * mean;
        float rstd  = rsqrtf(var + 1e-5f);
        float sc    = rstd * __ldg(gamma + threadIdx.x);
        g_scale[threadIdx.x] = sc;
        g_shift[threadIdx.x] = __ldg(beta + threadIdx.x) - mean * sc;
    }
}

// ---------------------------------------------------------------------------
// K3: elementwise BN-apply + LeakyReLU, float4 vectorized.
// ---------------------------------------------------------------------------
__global__ __launch_bounds__(256) void finalize_kernel(float* __restrict__ out, int n4) {
    int i = blockIdx.x * blockDim.x + threadIdx.x;
    if (i >= n4) return;
    float4 v = ((const float4*)g_conv)[i];
    int cb = (i & 7) * 4;                       // channel base within row
    float4 sc = *(const float4*)(g_scale + cb);
    float4 sh = *(const float4*)(g_shift + cb);
    float4 o;
    o.x = v.x * sc.x + sh.x;
    o.y = v.y * sc.y + sh.y;
    o.z = v.z * sc.z + sh.z;
    o.w = v.w * sc.w + sh.w;
    o.x = (o.x >= 0.f) ? o.x : 0.01f * o.x;
    o.y = (o.y >= 0.f) ? o.y : 0.01f * o.y;
    o.z = (o.z >= 0.f) ? o.z : 0.01f * o.z;
    o.w = (o.w >= 0.f) ? o.w : 0.01f * o.w;
    ((float4*)out)[i] = o;
}

// ---------------------------------------------------------------------------
// kernel_launch — inputs per metadata order:
//   0: features [N,32] f32   1: neighbor_idx [N,27] i32   2: weight [27,32,32] f32
//   3: bias [32] f32 (unused: cancels in training-mode BN)
//   4: gamma [32] f32        5: beta [32] f32
// output: [N,32] f32
// ---------------------------------------------------------------------------
extern "C" void kernel_launch(void* const* d_in, const int* in_sizes, int n_in,
                              void* d_out, int out_size)
{
    const float* feat  = (const float*)d_in[0];
    const int*   nbr   = (const int*)  d_in[1];
    const float* w     = (const float*)d_in[2];
    const float* gamma = (const float*)d_in[4];
    const float* beta  = (const float*)d_in[5];
    float* out = (float*)d_out;

    int n = in_sizes[0] / KCIN;     // number of active voxels
    if (n > NMAX) n = NMAX;

    transpose_w_kernel<<<(WELEMS + 255) / 256, 256>>>(w);
    conv_kernel<<<CBLOCKS, 128>>>(feat, nbr, n);
    stats_kernel<<<1, 1024>>>(gamma, beta, n);
    int n4 = n * (KCOUT / 4);
    finalize_kernel<<<(n4 + 255) / 256, 256>>>(out, n4);
}

// round 15
// speedup vs baseline: 1.0458x; 1.0386x over previous
#include <cuda_runtime.h>

#define NMAX    160000
#define KCOUT   32
#define KCIN    32
#define KTAPS   27
#define WELEMS  (KTAPS * KCIN * KCOUT)   // 27648
#define CBLOCKS 592                      // 4 warps/block -> 2368 warps = 1 wave @ 4 blocks/SM (128 regs)
#define NWARPS  (CBLOCKS * 4)

// ---- device scratch (no allocations allowed) ----
__device__ float g_conv[(size_t)NMAX * KCOUT];   // pre-BN conv output
__device__ float g_wt[WELEMS];                   // transposed weights [k][c/4][d][c%4]
__device__ float g_psum[CBLOCKS * KCOUT];        // per-block channel sums
__device__ float g_psq [CBLOCKS * KCOUT];        // per-block channel sum-of-squares
__device__ float g_scale[KCOUT];                 // rstd * gamma
__device__ float g_shift[KCOUT];                 // beta - mean * scale

// ---------------------------------------------------------------------------
// K0: transpose weight [k][c][d] -> [k][c>>2][d][c&3] so that lane d can load
//     a float4 covering 4 consecutive c for its output channel (coalesced).
// ---------------------------------------------------------------------------
__global__ void transpose_w_kernel(const float* __restrict__ w) {
    int i = blockIdx.x * blockDim.x + threadIdx.x;
    if (i < WELEMS) {
        int d = i & 31;
        int c = (i >> 5) & 31;
        int k = i >> 10;
        g_wt[k * 1024 + (c >> 2) * 128 + d * 4 + (c & 3)] = w[i];
    }
}

// ---------------------------------------------------------------------------
// K1: sparse conv (R8 structure + chain-break + ping-pong pipeline).
//     - center tap (k=13) == row itself (submanifold identity): dense stream
//     - center weights register-resident (32 regs)
//     - row loop unrolled x2 with A/B buffers: pipeline depth 1, zero reg MOVs
//     - 4 independent accumulators break the 32-deep FFMA RAW chain
//     - bias omitted (cancels exactly in training-mode BN)
// ---------------------------------------------------------------------------
__global__ __launch_bounds__(128, 4) void conv_kernel(
    const float* __restrict__ feat,   // [N,32]
    const int*   __restrict__ nbr,    // [N,27]
    int n)
{
    __shared__ float s_red[2][4][32];

    const int lane = threadIdx.x & 31;
    const int wloc = threadIdx.x >> 5;
    const int warp = blockIdx.x * 4 + wloc;

    // Center-tap (k=13) weights: lane d holds W[13][c][d] for all c, in regs.
    const float4* wcp = (const float4*)(g_wt + 13 * 1024) + lane;
    float4 wc[8];
    #pragma unroll
    for (int c4 = 0; c4 < 8; ++c4) wc[c4] = __ldg(wcp + c4 * 32);

    const unsigned EXTRA_MASK = ((1u << KTAPS) - 1u) & ~(1u << 13);

    const int per = (n + NWARPS - 1) / NWARPS;   // 68
    const int r0  = warp * per;
    const int r1  = (r0 + per < n) ? (r0 + per) : n;

    float bsum = 0.f, bsq = 0.f;

    float4 fA[8], fB[8];
    int idxA = -1, idxB = -1;

    // one-row processing body: center (4 acc chains) + rare extra taps
    auto compute = [&](const float4 (&f)[8], int idx, int row) {
        float a0 = 0.f, a1 = 0.f, a2 = 0.f, a3 = 0.f;
        #pragma unroll
        for (int c4 = 0; c4 < 8; c4 += 4) {
            a0 += f[c4+0].x*wc[c4+0].x + f[c4+0].y*wc[c4+0].y
                + f[c4+0].z*wc[c4+0].z + f[c4+0].w*wc[c4+0].w;
            a1 += f[c4+1].x*wc[c4+1].x + f[c4+1].y*wc[c4+1].y
                + f[c4+1].z*wc[c4+1].z + f[c4+1].w*wc[c4+1].w;
            a2 += f[c4+2].x*wc[c4+2].x + f[c4+2].y*wc[c4+2].y
                + f[c4+2].z*wc[c4+2].z + f[c4+2].w*wc[c4+2].w;
            a3 += f[c4+3].x*wc[c4+3].x + f[c4+3].y*wc[c4+3].y
                + f[c4+3].z*wc[c4+3].z + f[c4+3].w*wc[c4+3].w;
        }
        float acc = (a0 + a1) + (a2 + a3);

        // rare extra taps (~0.49/row average)
        unsigned m = __ballot_sync(0xffffffffu, idx >= 0) & EXTRA_MASK;
        while (m) {
            int k = __ffs(m) - 1;
            m &= (m - 1);
            int j = __shfl_sync(0xffffffffu, idx, k);

            const float4* fp2 = (const float4*)(feat + (long)j * 32);
            const float4* wp  = (const float4*)(g_wt + k * 1024) + lane;

            float e0 = 0.f, e1 = 0.f;
            #pragma unroll
            for (int h = 0; h < 4; ++h) {           // 2 float4 pairs per chunk
                float4 fa = __ldg(fp2 + 2*h);
                float4 fb = __ldg(fp2 + 2*h + 1);
                float4 wa = __ldg(wp + (2*h) * 32);
                float4 wb = __ldg(wp + (2*h + 1) * 32);
                e0 += fa.x*wa.x + fa.y*wa.y + fa.z*wa.z + fa.w*wa.w;
                e1 += fb.x*wb.x + fb.y*wb.y + fb.z*wb.z + fb.w*wb.w;
            }
            acc += e0 + e1;
        }

        g_conv[(long)row * KCOUT + lane] = acc;
        bsum += acc;
        bsq  += acc * acc;
    };

    if (r0 < r1) {
        // preload first row into A
        {
            const float4* fp = (const float4*)(feat + (long)r0 * 32);
            #pragma unroll
            for (int t = 0; t < 8; ++t) fA[t] = __ldg(fp + t);
            idxA = (lane < KTAPS) ? __ldg(nbr + (long)r0 * KTAPS + lane) : -1;
        }

        for (int row = r0; row < r1; row += 2) {
            // prefetch row+1 into B (flies over compute(A))
            if (row + 1 < r1) {
                const float4* fp = (const float4*)(feat + (long)(row + 1) * 32);
                #pragma unroll
                for (int t = 0; t < 8; ++t) fB[t] = __ldg(fp + t);
                idxB = (lane < KTAPS) ? __ldg(nbr + (long)(row + 1) * KTAPS + lane) : -1;
            }

            compute(fA, idxA, row);

            // prefetch row+2 into A (flies over compute(B))
            if (row + 2 < r1) {
                const float4* fp = (const float4*)(feat + (long)(row + 2) * 32);
                #pragma unroll
                for (int t = 0; t < 8; ++t) fA[t] = __ldg(fp + t);
                idxA = (lane < KTAPS) ? __ldg(nbr + (long)(row + 2) * KTAPS + lane) : -1;
            }

            if (row + 1 < r1) compute(fB, idxB, row + 1);
        }
    }

    // block-level deterministic reduction of BN partials
    s_red[0][wloc][lane] = bsum;
    s_red[1][wloc][lane] = bsq;
    __syncthreads();
    if (threadIdx.x < 32) {
        float s = 0.f, q = 0.f;
        #pragma unroll
        for (int i = 0; i < 4; ++i) { s += s_red[0][i][threadIdx.x]; q += s_red[1][i][threadIdx.x]; }
        g_psum[blockIdx.x * 32 + threadIdx.x] = s;
        g_psq [blockIdx.x * 32 + threadIdx.x] = q;
    }
}

// ---------------------------------------------------------------------------
// K2: reduce block partials -> mean/var -> fused scale/shift. Single block.
// ---------------------------------------------------------------------------
__global__ void stats_kernel(const float* __restrict__ gamma,
                             const float* __restrict__ beta,
                             int n)
{
    __shared__ float ss[32][32];
    __shared__ float sq[32][32];
    const int ch = threadIdx.x & 31;
    const int sl = threadIdx.x >> 5;   // 1024 threads -> 32 slices

    float s = 0.f, q = 0.f;
    for (int i = sl; i < CBLOCKS; i += 32) {
        s += g_psum[i * 32 + ch];
        q += g_psq [i * 32 + ch];
    }
    ss[sl][ch] = s;
    sq[sl][ch] = q;
    __syncthreads();

    if (threadIdx.x < 32) {
        float S = 0.f, Q = 0.f;
        #pragma unroll
        for (int i = 0; i < 32; ++i) { S += ss[i][threadIdx.x]; Q += sq[i][threadIdx.x]; }
        float inv_n = 1.f / (float)n;
        float mean  = S * inv_n;
        float var   = Q * inv_n - mean * mean;
        float rstd  = rsqrtf(var + 1e-5f);
        float sc    = rstd * __ldg(gamma + threadIdx.x);
        g_scale[threadIdx.x] = sc;
        g_shift[threadIdx.x] = __ldg(beta + threadIdx.x) - mean * sc;
    }
}

// ---------------------------------------------------------------------------
// K3: elementwise BN-apply + LeakyReLU, float4 vectorized.
// ---------------------------------------------------------------------------
__global__ __launch_bounds__(256) void finalize_kernel(float* __restrict__ out, int n4) {
    int i = blockIdx.x * blockDim.x + threadIdx.x;
    if (i >= n4) return;
    float4 v = ((const float4*)g_conv)[i];
    int cb = (i & 7) * 4;                       // channel base within row
    float4 sc = *(const float4*)(g_scale + cb);
    float4 sh = *(const float4*)(g_shift + cb);
    float4 o;
    o.x = v.x * sc.x + sh.x;
    o.y = v.y * sc.y + sh.y;
    o.z = v.z * sc.z + sh.z;
    o.w = v.w * sc.w + sh.w;
    o.x = (o.x >= 0.f) ? o.x : 0.01f * o.x;
    o.y = (o.y >= 0.f) ? o.y : 0.01f * o.y;
    o.z = (o.z >= 0.f) ? o.z : 0.01f * o.z;
    o.w = (o.w >= 0.f) ? o.w : 0.01f * o.w;
    ((float4*)out)[i] = o;
}

// ---------------------------------------------------------------------------
// kernel_launch — inputs per metadata order:
//   0: features [N,32] f32   1: neighbor_idx [N,27] i32   2: weight [27,32,32] f32
//   3: bias [32] f32 (unused: cancels in training-mode BN)
//   4: gamma [32] f32        5: beta [32] f32
// output: [N,32] f32
// ---------------------------------------------------------------------------
extern "C" void kernel_launch(void* const* d_in, const int* in_sizes, int n_in,
                              void* d_out, int out_size)
{
    const float* feat  = (const float*)d_in[0];
    const int*   nbr   = (const int*)  d_in[1];
    const float* w     = (const float*)d_in[2];
    const float* gamma = (const float*)d_in[4];
    const float* beta  = (const float*)d_in[5];
    float* out = (float*)d_out;

    int n = in_sizes[0] / KCIN;     // number of active voxels
    if (n > NMAX) n = NMAX;

    transpose_w_kernel<<<(WELEMS + 255) / 256, 256>>>(w);
    conv_kernel<<<CBLOCKS, 128>>>(feat, nbr, n);
    stats_kernel<<<1, 1024>>>(gamma, beta, n);
    int n4 = n * (KCOUT / 4);
    finalize_kernel<<<(n4 + 255) / 256, 256>>>(out, n4);
}

// round 16
// speedup vs baseline: 1.3017x; 1.2447x over previous
#include <cuda_runtime.h>

#define NMAX    160000
#define KCOUT   32
#define KCIN    32
#define KTAPS   27
#define WELEMS  (KTAPS * KCIN * KCOUT)   // 27648
#define CBLOCKS 625                      // 4 warps/block -> 2500 warps; 64 rows/warp = 2 full 32-row batches
#define NWARPS  (CBLOCKS * 4)

// ---- device scratch (no allocations allowed) ----
__device__ float g_conv[(size_t)NMAX * KCOUT];   // pre-BN conv output
__device__ float g_wt[WELEMS];                   // transposed weights [k][c/4][d][c%4] (extras path)
__device__ float g_psum[CBLOCKS * KCOUT];        // per-block channel sums
__device__ float g_psq [CBLOCKS * KCOUT];        // per-block channel sum-of-squares
__device__ float g_scale[KCOUT];                 // rstd * gamma
__device__ float g_shift[KCOUT];                 // beta - mean * scale

// ---------------------------------------------------------------------------
// K0: transpose weight [k][c][d] -> [k][c>>2][d][c&3] for the extras path
//     (lane d loads a float4 covering 4 consecutive c, coalesced).
// ---------------------------------------------------------------------------
__global__ void transpose_w_kernel(const float* __restrict__ w) {
    int i = blockIdx.x * blockDim.x + threadIdx.x;
    if (i < WELEMS) {
        int d = i & 31;
        int c = (i >> 5) & 31;
        int k = i >> 10;
        g_wt[k * 1024 + (c >> 2) * 128 + d * 4 + (c & 3)] = w[i];
    }
}

// ---------------------------------------------------------------------------
// K1: sparse conv, 32-row batch version.
//     Phase A (per batch): front-load ALL long-latency data for 32 rows
//       (8 feature LDG.128 per thread-own-row + 27 coalesced idx LDG -> SMEM).
//     Phase B: center tap (k=13 == row itself) thread-per-row: 32 accs,
//       W13 broadcast from SMEM.
//     Phase C: stage accs to SMEM, then per-row lane=channel pass:
//       warp-cooperative rare extras (ballot from SMEM idx), coalesced store,
//       BN partials. Bias omitted (cancels exactly in training-mode BN).
// ---------------------------------------------------------------------------
__global__ __launch_bounds__(128, 5) void conv_kernel(
    const float* __restrict__ feat,   // [N,32]
    const int*   __restrict__ nbr,    // [N,27]
    const float* __restrict__ w,      // [27,32,32] original layout (center tap)
    int n)
{
    __shared__ float s_w13[1024];        // W[13][c][d], d contiguous (as in input)
    __shared__ int   s_idx[4][32 * KTAPS];
    __shared__ float s_out[4][32][36];   // +4 pad: conflict-free strided STS128
    __shared__ float s_red[2][4][32];

    const int tid  = threadIdx.x;
    const int lane = tid & 31;
    const int wloc = tid >> 5;
    const int warp = blockIdx.x * 4 + wloc;

    // cooperative load of center-tap weights into SMEM (2 float4 per thread)
    {
        const float4* ws = (const float4*)(w + 13 * 1024);
        ((float4*)s_w13)[tid]       = __ldg(ws + tid);
        ((float4*)s_w13)[tid + 128] = __ldg(ws + tid + 128);
    }
    __syncthreads();

    const unsigned EXTRA_MASK = ((1u << KTAPS) - 1u) & ~(1u << 13);

    const int per = (n + NWARPS - 1) / NWARPS;   // 64 for n=160000
    const int r0  = warp * per;
    const int r1  = (r0 + per < n) ? (r0 + per) : n;

    float bsum = 0.f, bsq = 0.f;

    for (int base = r0; base < r1; base += 32) {
        const int nrows = (r1 - base < 32) ? (r1 - base) : 32;

        // ---- Phase A: front-load idx (coalesced, into SMEM) ----
        const int nelem = nrows * KTAPS;
        for (int j = lane; j < nelem; j += 32)
            s_idx[wloc][j] = __ldg(nbr + (long)base * KTAPS + j);

        // ---- Phase B: center tap, thread owns row base+lane ----
        float4 acc[8];
        #pragma unroll
        for (int dc = 0; dc < 8; ++dc) acc[dc] = make_float4(0.f, 0.f, 0.f, 0.f);

        if (lane < nrows) {
            const float4* fp = (const float4*)(feat + (long)(base + lane) * 32);
            #pragma unroll
            for (int c4 = 0; c4 < 8; ++c4) {
                float4 f4 = __ldg(fp + c4);
                #pragma unroll
                for (int cc = 0; cc < 4; ++cc) {
                    const float fc = (cc == 0) ? f4.x : (cc == 1) ? f4.y
                                   : (cc == 2) ? f4.z : f4.w;
                    const float4* wrow = (const float4*)(s_w13 + (c4 * 4 + cc) * 32);
                    #pragma unroll
                    for (int dc = 0; dc < 8; ++dc) {
                        float4 wv = wrow[dc];            // LDS128 broadcast
                        acc[dc].x += fc * wv.x;
                        acc[dc].y += fc * wv.y;
                        acc[dc].z += fc * wv.z;
                        acc[dc].w += fc * wv.w;
                    }
                }
            }
        }

        // ---- stage accs: thread's row -> s_out[wloc][lane][*] ----
        #pragma unroll
        for (int dc = 0; dc < 8; ++dc)
            *(float4*)&s_out[wloc][lane][dc * 4] = acc[dc];
        __syncwarp();

        // ---- Phase C: per-row finish, lane = output channel ----
        for (int r = 0; r < nrows; ++r) {
            float v  = s_out[wloc][r][lane];
            int  idx = (lane < KTAPS) ? s_idx[wloc][r * KTAPS + lane] : -1;

            unsigned m = __ballot_sync(0xffffffffu, idx >= 0) & EXTRA_MASK;
            while (m) {
                int k = __ffs(m) - 1;
                m &= (m - 1);
                int j = __shfl_sync(0xffffffffu, idx, k);

                const float4* fp2 = (const float4*)(feat + (long)j * 32);
                const float4* wp  = (const float4*)(g_wt + k * 1024) + lane;

                float e0 = 0.f, e1 = 0.f;
                #pragma unroll
                for (int h = 0; h < 4; ++h) {
                    float4 fa = __ldg(fp2 + 2 * h);
                    float4 fb = __ldg(fp2 + 2 * h + 1);
                    float4 wa = __ldg(wp + (2 * h) * 32);
                    float4 wb = __ldg(wp + (2 * h + 1) * 32);
                    e0 += fa.x * wa.x + fa.y * wa.y + fa.z * wa.z + fa.w * wa.w;
                    e1 += fb.x * wb.x + fb.y * wb.y + fb.z * wb.z + fb.w * wb.w;
                }
                v += e0 + e1;
            }

            g_conv[(long)(base + r) * KCOUT + lane] = v;   // coalesced
            bsum += v;
            bsq  += v * v;
        }
        __syncwarp();   // protect s_idx/s_out before next batch
    }

    // block-level deterministic reduction of BN partials
    s_red[0][wloc][lane] = bsum;
    s_red[1][wloc][lane] = bsq;
    __syncthreads();
    if (tid < 32) {
        float s = 0.f, q = 0.f;
        #pragma unroll
        for (int i = 0; i < 4; ++i) { s += s_red[0][i][tid]; q += s_red[1][i][tid]; }
        g_psum[blockIdx.x * 32 + tid] = s;
        g_psq [blockIdx.x * 32 + tid] = q;
    }
}

// ---------------------------------------------------------------------------
// K2: reduce block partials -> mean/var -> fused scale/shift. Single block.
// ---------------------------------------------------------------------------
__global__ void stats_kernel(const float* __restrict__ gamma,
                             const float* __restrict__ beta,
                             int n)
{
    __shared__ float ss[32][32];
    __shared__ float sq[32][32];
    const int ch = threadIdx.x & 31;
    const int sl = threadIdx.x >> 5;   // 1024 threads -> 32 slices

    float s = 0.f, q = 0.f;
    for (int i = sl; i < CBLOCKS; i += 32) {
        s += g_psum[i * 32 + ch];
        q += g_psq [i * 32 + ch];
    }
    ss[sl][ch] = s;
    sq[sl][ch] = q;
    __syncthreads();

    if (threadIdx.x < 32) {
        float S = 0.f, Q = 0.f;
        #pragma unroll
        for (int i = 0; i < 32; ++i) { S += ss[i][threadIdx.x]; Q += sq[i][threadIdx.x]; }
        float inv_n = 1.f / (float)n;
        float mean  = S * inv_n;
        float var   = Q * inv_n - mean * mean;
        float rstd  = rsqrtf(var + 1e-5f);
        float sc    = rstd * __ldg(gamma + threadIdx.x);
        g_scale[threadIdx.x] = sc;
        g_shift[threadIdx.x] = __ldg(beta + threadIdx.x) - mean * sc;
    }
}

// ---------------------------------------------------------------------------
// K3: elementwise BN-apply + LeakyReLU, float4 vectorized.
// ---------------------------------------------------------------------------
__global__ __launch_bounds__(256) void finalize_kernel(float* __restrict__ out, int n4) {
    int i = blockIdx.x * blockDim.x + threadIdx.x;
    if (i >= n4) return;
    float4 v = ((const float4*)g_conv)[i];
    int cb = (i & 7) * 4;                       // channel base within row
    float4 sc = *(const float4*)(g_scale + cb);
    float4 sh = *(const float4*)(g_shift + cb);
    float4 o;
    o.x = v.x * sc.x + sh.x;
    o.y = v.y * sc.y + sh.y;
    o.z = v.z * sc.z + sh.z;
    o.w = v.w * sc.w + sh.w;
    o.x = (o.x >= 0.f) ? o.x : 0.01f * o.x;
    o.y = (o.y >= 0.f) ? o.y : 0.01f * o.y;
    o.z = (o.z >= 0.f) ? o.z : 0.01f * o.z;
    o.w = (o.w >= 0.f) ? o.w : 0.01f * o.w;
    ((float4*)out)[i] = o;
}

// ---------------------------------------------------------------------------
// kernel_launch — inputs per metadata order:
//   0: features [N,32] f32   1: neighbor_idx [N,27] i32   2: weight [27,32,32] f32
//   3: bias [32] f32 (unused: cancels in training-mode BN)
//   4: gamma [32] f32        5: beta [32] f32
// output: [N,32] f32
// ---------------------------------------------------------------------------
extern "C" void kernel_launch(void* const* d_in, const int* in_sizes, int n_in,
                              void* d_out, int out_size)
{
    const float* feat  = (const float*)d_in[0];
    const int*   nbr   = (const int*)  d_in[1];
    const float* w     = (const float*)d_in[2];
    const float* gamma = (const float*)d_in[4];
    const float* beta  = (const float*)d_in[5];
    float* out = (float*)d_out;

    int n = in_sizes[0] / KCIN;     // number of active voxels
    if (n > NMAX) n = NMAX;

    transpose_w_kernel<<<(WELEMS + 255) / 256, 256>>>(w);
    conv_kernel<<<CBLOCKS, 128>>>(feat, nbr, w, n);
    stats_kernel<<<1, 1024>>>(gamma, beta, n);
    int n4 = n * (KCOUT / 4);
    finalize_kernel<<<(n4 + 255) / 256, 256>>>(out, n4);
}